// round 7
// baseline (speedup 1.0000x reference)
#include <cuda_runtime.h>
#include <cuda_bf16.h>
#include <math.h>

// Problem constants
#define BATCH 2
#define SEQ 2048
#define DMODEL 1024
#define NHEADS 16
#define DK 64
#define MROWS (BATCH * SEQ)   // 4096

// Scratch buffers (device globals: no allocation allowed in kernel_launch)
__device__ float g_Q[MROWS * DMODEL];
__device__ float g_K[MROWS * DMODEL];
__device__ float g_V[MROWS * DMODEL];
__device__ float g_O[MROWS * DMODEL];

// ----------------------------------------------------------------------------
// GEMM (NT): C[m,n] = sum_k A[m,k] * W[n,k]   (A: MxK, W: NxK, both K-contig)
// Tile 64x64, BK=16, 256 threads, 4x4 micro-tile per thread.
// ----------------------------------------------------------------------------
#define BK 16

__global__ void __launch_bounds__(256) gemm_nt(const float* __restrict__ A,
                                               const float* __restrict__ Wm,
                                               float* __restrict__ C,
                                               int M, int N, int K) {
    __shared__ float As[BK][68];   // K-major, pad 68 (float4 aligned)
    __shared__ float Ws[BK][68];

    const int tid = threadIdx.x;
    const int tx = tid & 15;       // 0..15 -> N direction
    const int ty = tid >> 4;       // 0..15 -> M direction
    const int m0 = blockIdx.y * 64;
    const int n0 = blockIdx.x * 64;

    // cooperative load mapping: 256 threads cover 64 rows x 16 K-cols (float4)
    const int lr = tid >> 2;           // 0..63 row within tile
    const int lc = (tid & 3) * 4;      // 0,4,8,12 k-col within tile

    const float* aLoad = A  + (size_t)(m0 + lr) * K + lc;
    const float* wLoad = Wm + (size_t)(n0 + lr) * K + lc;

    float acc[4][4];
#pragma unroll
    for (int i = 0; i < 4; i++)
#pragma unroll
        for (int j = 0; j < 4; j++) acc[i][j] = 0.f;

    for (int k0 = 0; k0 < K; k0 += BK) {
        float4 av = *(const float4*)(aLoad + k0);
        float4 wv = *(const float4*)(wLoad + k0);
        As[lc + 0][lr] = av.x; As[lc + 1][lr] = av.y;
        As[lc + 2][lr] = av.z; As[lc + 3][lr] = av.w;
        Ws[lc + 0][lr] = wv.x; Ws[lc + 1][lr] = wv.y;
        Ws[lc + 2][lr] = wv.z; Ws[lc + 3][lr] = wv.w;
        __syncthreads();

#pragma unroll
        for (int kk = 0; kk < BK; kk++) {
            float4 a = *(const float4*)&As[kk][ty * 4];
            float4 b = *(const float4*)&Ws[kk][tx * 4];
            float ar[4] = {a.x, a.y, a.z, a.w};
            float br[4] = {b.x, b.y, b.z, b.w};
#pragma unroll
            for (int i = 0; i < 4; i++)
#pragma unroll
                for (int j = 0; j < 4; j++)
                    acc[i][j] += ar[i] * br[j];
        }
        __syncthreads();
    }

#pragma unroll
    for (int i = 0; i < 4; i++) {
        float4 o = make_float4(acc[i][0], acc[i][1], acc[i][2], acc[i][3]);
        *(float4*)&C[(size_t)(m0 + ty * 4 + i) * N + n0 + tx * 4] = o;
    }
}

// ----------------------------------------------------------------------------
// RoPE (in-place on Q and K, natural [B,S,D] layout).
// Double-precision angle: pos up to 2047 amplifies freq error, so fp32 powf
// would cost ~1e-3 in sin/cos. Double keeps us <= the reference's own rounding.
// ----------------------------------------------------------------------------
__global__ void rope_kernel(float* __restrict__ Qb, float* __restrict__ Kb,
                            const int* __restrict__ tp) {
    int idx = blockIdx.x * blockDim.x + threadIdx.x;   // over B*S*(D/2)
    if (idx >= BATCH * SEQ * (DMODEL / 2)) return;
    int d2 = idx & (DMODEL / 2 - 1);   // 0..511
    int bs = idx >> 9;                 // 0..4095 (b*S+s)
    int s  = bs & (SEQ - 1);
    int h  = d2 >> 5;                  // head
    int i  = d2 & 31;                  // pair index within head

    double pos  = (double)tp[s];
    // theta^(-(2i)/64) = exp(-(2i/64) * ln(10000))
    double freq = exp(-((double)(2 * i) / 64.0) * 9.210340371976184);
    double ang  = pos * freq;
    float cs = (float)cos(ang);
    float sn = (float)sin(ang);

    size_t base = (size_t)bs * DMODEL + h * DK + 2 * i;
    float q1 = Qb[base], q2 = Qb[base + 1];
    Qb[base]     = q1 * cs - q2 * sn;
    Qb[base + 1] = q1 * sn + q2 * cs;
    float k1 = Kb[base], k2 = Kb[base + 1];
    Kb[base]     = k1 * cs - k2 * sn;
    Kb[base + 1] = k1 * sn + k2 * cs;
}

// ----------------------------------------------------------------------------
// Causal flash attention. One block = one (b, h, 64-row q tile).
// 64 threads: thread t owns query row t. Q row + O accumulator in registers.
// Smem: K tile + V tile + transposed score tile = exactly 48 KB.
// ----------------------------------------------------------------------------
__global__ void __launch_bounds__(64) attn_kernel(const float* __restrict__ Q,
                                                  const float* __restrict__ K,
                                                  const float* __restrict__ V,
                                                  float* __restrict__ O) {
    __shared__ float Ks[64 * 64];
    __shared__ float Vs[64 * 64];
    __shared__ float scr[64 * 64];   // scr[k*64 + t]: bank = lane, conflict-free

    const int t  = threadIdx.x;       // query row within tile
    const int qt = blockIdx.x;        // q tile index
    const int h  = blockIdx.y;
    const int b  = blockIdx.z;
    const int q0 = qt * 64;

    const float* qptr = Q + ((size_t)(b * SEQ + q0 + t)) * DMODEL + h * DK;
    float q[DK];
#pragma unroll
    for (int d = 0; d < DK; d += 4) {
        float4 v4 = *(const float4*)(qptr + d);
        q[d] = v4.x; q[d + 1] = v4.y; q[d + 2] = v4.z; q[d + 3] = v4.w;
    }
    float o[DK];
#pragma unroll
    for (int d = 0; d < DK; d++) o[d] = 0.f;
    float m = -1e30f, l = 0.f;

    for (int kt = 0; kt <= qt; kt++) {
        const float* kbase = K + ((size_t)(b * SEQ + kt * 64)) * DMODEL + h * DK;
        const float* vbase = V + ((size_t)(b * SEQ + kt * 64)) * DMODEL + h * DK;
        // cooperative coalesced tile load: 1024 float4s / 64 threads
#pragma unroll
        for (int it = 0; it < 16; it++) {
            int flat4 = it * 64 + t;
            int kr = flat4 >> 4;
            int d4 = (flat4 & 15) * 4;
            *(float4*)&Ks[kr * 64 + d4] = *(const float4*)(kbase + (size_t)kr * DMODEL + d4);
            *(float4*)&Vs[kr * 64 + d4] = *(const float4*)(vbase + (size_t)kr * DMODEL + d4);
        }
        __syncthreads();

        const int kmax = (kt == qt) ? (t + 1) : 64;   // causal

        float tm = -1e30f;
        for (int k = 0; k < kmax; k++) {
            float s = 0.f;
#pragma unroll
            for (int d = 0; d < DK; d += 4) {
                float4 kv = *(const float4*)&Ks[k * 64 + d];
                s += q[d] * kv.x + q[d + 1] * kv.y + q[d + 2] * kv.z + q[d + 3] * kv.w;
            }
            s *= 0.125f;   // 1/sqrt(64)
            scr[k * 64 + t] = s;
            tm = fmaxf(tm, s);
        }

        float mn   = fmaxf(m, tm);
        float corr = __expf(m - mn);
        float lsum = 0.f;
        for (int k = 0; k < kmax; k++) {
            float p = __expf(scr[k * 64 + t] - mn);
            scr[k * 64 + t] = p;
            lsum += p;
        }
        l = l * corr + lsum;
#pragma unroll
        for (int d = 0; d < DK; d++) o[d] *= corr;

        for (int k = 0; k < kmax; k++) {
            float p = scr[k * 64 + t];
#pragma unroll
            for (int d = 0; d < DK; d += 4) {
                float4 vv = *(const float4*)&Vs[k * 64 + d];
                o[d]     += p * vv.x;
                o[d + 1] += p * vv.y;
                o[d + 2] += p * vv.z;
                o[d + 3] += p * vv.w;
            }
        }
        m = mn;
        __syncthreads();
    }

    float inv = 1.f / l;
    float* optr = O + ((size_t)(b * SEQ + q0 + t)) * DMODEL + h * DK;
#pragma unroll
    for (int d = 0; d < DK; d += 4) {
        float4 v4 = make_float4(o[d] * inv, o[d + 1] * inv, o[d + 2] * inv, o[d + 3] * inv);
        *(float4*)(optr + d) = v4;
    }
}

// ----------------------------------------------------------------------------
// Launch
// ----------------------------------------------------------------------------
extern "C" void kernel_launch(void* const* d_in, const int* in_sizes, int n_in,
                              void* d_out, int out_size) {
    (void)in_sizes; (void)n_in; (void)out_size;
    const float* x  = (const float*)d_in[0];
    const int*   tp = (const int*)d_in[1];
    const float* Wq = (const float*)d_in[2];
    const float* Wk = (const float*)d_in[3];
    const float* Wv = (const float*)d_in[4];
    const float* Wo = (const float*)d_in[5];
    float* out = (float*)d_out;

    float *Qp, *Kp, *Vp, *Op;
    cudaGetSymbolAddress((void**)&Qp, g_Q);
    cudaGetSymbolAddress((void**)&Kp, g_K);
    cudaGetSymbolAddress((void**)&Vp, g_V);
    cudaGetSymbolAddress((void**)&Op, g_O);

    dim3 gg(DMODEL / 64, MROWS / 64);   // (16, 64)
    gemm_nt<<<gg, 256>>>(x, Wq, Qp, MROWS, DMODEL, DMODEL);
    gemm_nt<<<gg, 256>>>(x, Wk, Kp, MROWS, DMODEL, DMODEL);
    gemm_nt<<<gg, 256>>>(x, Wv, Vp, MROWS, DMODEL, DMODEL);

    int ropeN = BATCH * SEQ * (DMODEL / 2);
    rope_kernel<<<(ropeN + 255) / 256, 256>>>(Qp, Kp, tp);

    attn_kernel<<<dim3(SEQ / 64, NHEADS, BATCH), 64>>>(Qp, Kp, Vp, Op);

    gemm_nt<<<gg, 256>>>(Op, Wo, out, MROWS, DMODEL, DMODEL);
}

// round 8
// speedup vs baseline: 1.0081x; 1.0081x over previous
#include <cuda_runtime.h>
#include <cuda_bf16.h>
#include <math.h>

// Problem constants
#define BATCH 2
#define SEQ 2048
#define DMODEL 1024
#define NHEADS 16
#define DK 64
#define MROWS (BATCH * SEQ)   // 4096

// Scratch buffers (device globals: no allocation allowed in kernel_launch)
__device__ float g_Q[MROWS * DMODEL];
__device__ float g_K[MROWS * DMODEL];
__device__ float g_V[MROWS * DMODEL];
__device__ float g_O[MROWS * DMODEL];

// ----------------------------------------------------------------------------
// GEMM (NT): C[m,n] = sum_k A[m,k] * W[n,k]   (A: MxK, W: NxK, both K-contig)
// Tile 64x64, BK=16, 256 threads, 4x4 micro-tile per thread.
// ----------------------------------------------------------------------------
#define BK 16

__global__ void __launch_bounds__(256) gemm_nt(const float* __restrict__ A,
                                               const float* __restrict__ Wm,
                                               float* __restrict__ C,
                                               int M, int N, int K) {
    __shared__ float As[BK][68];   // K-major, pad 68 (float4 aligned)
    __shared__ float Ws[BK][68];

    const int tid = threadIdx.x;
    const int tx = tid & 15;       // 0..15 -> N direction
    const int ty = tid >> 4;       // 0..15 -> M direction
    const int m0 = blockIdx.y * 64;
    const int n0 = blockIdx.x * 64;

    // cooperative load mapping: 256 threads cover 64 rows x 16 K-cols (float4)
    const int lr = tid >> 2;           // 0..63 row within tile
    const int lc = (tid & 3) * 4;      // 0,4,8,12 k-col within tile

    const float* aLoad = A  + (size_t)(m0 + lr) * K + lc;
    const float* wLoad = Wm + (size_t)(n0 + lr) * K + lc;

    float acc[4][4];
#pragma unroll
    for (int i = 0; i < 4; i++)
#pragma unroll
        for (int j = 0; j < 4; j++) acc[i][j] = 0.f;

    for (int k0 = 0; k0 < K; k0 += BK) {
        float4 av = *(const float4*)(aLoad + k0);
        float4 wv = *(const float4*)(wLoad + k0);
        As[lc + 0][lr] = av.x; As[lc + 1][lr] = av.y;
        As[lc + 2][lr] = av.z; As[lc + 3][lr] = av.w;
        Ws[lc + 0][lr] = wv.x; Ws[lc + 1][lr] = wv.y;
        Ws[lc + 2][lr] = wv.z; Ws[lc + 3][lr] = wv.w;
        __syncthreads();

#pragma unroll
        for (int kk = 0; kk < BK; kk++) {
            float4 a = *(const float4*)&As[kk][ty * 4];
            float4 b = *(const float4*)&Ws[kk][tx * 4];
            float ar[4] = {a.x, a.y, a.z, a.w};
            float br[4] = {b.x, b.y, b.z, b.w};
#pragma unroll
            for (int i = 0; i < 4; i++)
#pragma unroll
                for (int j = 0; j < 4; j++)
                    acc[i][j] += ar[i] * br[j];
        }
        __syncthreads();
    }

#pragma unroll
    for (int i = 0; i < 4; i++) {
        float4 o = make_float4(acc[i][0], acc[i][1], acc[i][2], acc[i][3]);
        *(float4*)&C[(size_t)(m0 + ty * 4 + i) * N + n0 + tx * 4] = o;
    }
}

// ----------------------------------------------------------------------------
// RoPE (in-place on Q and K, natural [B,S,D] layout).
// Double-precision angle: pos up to 2047 amplifies freq error, so fp32 powf
// would cost ~1e-3 in sin/cos. Double keeps us <= the reference's own rounding.
// ----------------------------------------------------------------------------
__global__ void rope_kernel(float* __restrict__ Qb, float* __restrict__ Kb,
                            const int* __restrict__ tp) {
    int idx = blockIdx.x * blockDim.x + threadIdx.x;   // over B*S*(D/2)
    if (idx >= BATCH * SEQ * (DMODEL / 2)) return;
    int d2 = idx & (DMODEL / 2 - 1);   // 0..511
    int bs = idx >> 9;                 // 0..4095 (b*S+s)
    int s  = bs & (SEQ - 1);
    int h  = d2 >> 5;                  // head
    int i  = d2 & 31;                  // pair index within head

    double pos  = (double)tp[s];
    // theta^(-(2i)/64) = exp(-(2i/64) * ln(10000))
    double freq = exp(-((double)(2 * i) / 64.0) * 9.210340371976184);
    double ang  = pos * freq;
    float cs = (float)cos(ang);
    float sn = (float)sin(ang);

    size_t base = (size_t)bs * DMODEL + h * DK + 2 * i;
    float q1 = Qb[base], q2 = Qb[base + 1];
    Qb[base]     = q1 * cs - q2 * sn;
    Qb[base + 1] = q1 * sn + q2 * cs;
    float k1 = Kb[base], k2 = Kb[base + 1];
    Kb[base]     = k1 * cs - k2 * sn;
    Kb[base + 1] = k1 * sn + k2 * cs;
}

// ----------------------------------------------------------------------------
// Causal flash attention. One block = one (b, h, 64-row q tile).
// 64 threads: thread t owns query row t. Q row + O accumulator in registers.
// Smem: K tile + V tile + transposed score tile = exactly 48 KB.
// ----------------------------------------------------------------------------
__global__ void __launch_bounds__(64) attn_kernel(const float* __restrict__ Q,
                                                  const float* __restrict__ K,
                                                  const float* __restrict__ V,
                                                  float* __restrict__ O) {
    __shared__ float Ks[64 * 64];
    __shared__ float Vs[64 * 64];
    __shared__ float scr[64 * 64];   // scr[k*64 + t]: bank = lane, conflict-free

    const int t  = threadIdx.x;       // query row within tile
    const int qt = blockIdx.x;        // q tile index
    const int h  = blockIdx.y;
    const int b  = blockIdx.z;
    const int q0 = qt * 64;

    const float* qptr = Q + ((size_t)(b * SEQ + q0 + t)) * DMODEL + h * DK;
    float q[DK];
#pragma unroll
    for (int d = 0; d < DK; d += 4) {
        float4 v4 = *(const float4*)(qptr + d);
        q[d] = v4.x; q[d + 1] = v4.y; q[d + 2] = v4.z; q[d + 3] = v4.w;
    }
    float o[DK];
#pragma unroll
    for (int d = 0; d < DK; d++) o[d] = 0.f;
    float m = -1e30f, l = 0.f;

    for (int kt = 0; kt <= qt; kt++) {
        const float* kbase = K + ((size_t)(b * SEQ + kt * 64)) * DMODEL + h * DK;
        const float* vbase = V + ((size_t)(b * SEQ + kt * 64)) * DMODEL + h * DK;
        // cooperative coalesced tile load: 1024 float4s / 64 threads
#pragma unroll
        for (int it = 0; it < 16; it++) {
            int flat4 = it * 64 + t;
            int kr = flat4 >> 4;
            int d4 = (flat4 & 15) * 4;
            *(float4*)&Ks[kr * 64 + d4] = *(const float4*)(kbase + (size_t)kr * DMODEL + d4);
            *(float4*)&Vs[kr * 64 + d4] = *(const float4*)(vbase + (size_t)kr * DMODEL + d4);
        }
        __syncthreads();

        const int kmax = (kt == qt) ? (t + 1) : 64;   // causal

        float tm = -1e30f;
        for (int k = 0; k < kmax; k++) {
            float s = 0.f;
#pragma unroll
            for (int d = 0; d < DK; d += 4) {
                float4 kv = *(const float4*)&Ks[k * 64 + d];
                s += q[d] * kv.x + q[d + 1] * kv.y + q[d + 2] * kv.z + q[d + 3] * kv.w;
            }
            s *= 0.125f;   // 1/sqrt(64)
            scr[k * 64 + t] = s;
            tm = fmaxf(tm, s);
        }

        float mn   = fmaxf(m, tm);
        float corr = __expf(m - mn);
        float lsum = 0.f;
        for (int k = 0; k < kmax; k++) {
            float p = __expf(scr[k * 64 + t] - mn);
            scr[k * 64 + t] = p;
            lsum += p;
        }
        l = l * corr + lsum;
#pragma unroll
        for (int d = 0; d < DK; d++) o[d] *= corr;

        for (int k = 0; k < kmax; k++) {
            float p = scr[k * 64 + t];
#pragma unroll
            for (int d = 0; d < DK; d += 4) {
                float4 vv = *(const float4*)&Vs[k * 64 + d];
                o[d]     += p * vv.x;
                o[d + 1] += p * vv.y;
                o[d + 2] += p * vv.z;
                o[d + 3] += p * vv.w;
            }
        }
        m = mn;
        __syncthreads();
    }

    float inv = 1.f / l;
    float* optr = O + ((size_t)(b * SEQ + q0 + t)) * DMODEL + h * DK;
#pragma unroll
    for (int d = 0; d < DK; d += 4) {
        float4 v4 = make_float4(o[d] * inv, o[d + 1] * inv, o[d + 2] * inv, o[d + 3] * inv);
        *(float4*)(optr + d) = v4;
    }
}

// ----------------------------------------------------------------------------
// Launch
// ----------------------------------------------------------------------------
extern "C" void kernel_launch(void* const* d_in, const int* in_sizes, int n_in,
                              void* d_out, int out_size) {
    (void)in_sizes; (void)n_in; (void)out_size;
    const float* x  = (const float*)d_in[0];
    const int*   tp = (const int*)d_in[1];
    const float* Wq = (const float*)d_in[2];
    const float* Wk = (const float*)d_in[3];
    const float* Wv = (const float*)d_in[4];
    const float* Wo = (const float*)d_in[5];
    float* out = (float*)d_out;

    float *Qp, *Kp, *Vp, *Op;
    cudaGetSymbolAddress((void**)&Qp, g_Q);
    cudaGetSymbolAddress((void**)&Kp, g_K);
    cudaGetSymbolAddress((void**)&Vp, g_V);
    cudaGetSymbolAddress((void**)&Op, g_O);

    dim3 gg(DMODEL / 64, MROWS / 64);   // (16, 64)
    gemm_nt<<<gg, 256>>>(x, Wq, Qp, MROWS, DMODEL, DMODEL);
    gemm_nt<<<gg, 256>>>(x, Wk, Kp, MROWS, DMODEL, DMODEL);
    gemm_nt<<<gg, 256>>>(x, Wv, Vp, MROWS, DMODEL, DMODEL);

    int ropeN = BATCH * SEQ * (DMODEL / 2);
    rope_kernel<<<(ropeN + 255) / 256, 256>>>(Qp, Kp, tp);

    attn_kernel<<<dim3(SEQ / 64, NHEADS, BATCH), 64>>>(Qp, Kp, Vp, Op);

    gemm_nt<<<gg, 256>>>(Op, Wo, out, MROWS, DMODEL, DMODEL);
}